// round 11
// baseline (speedup 1.0000x reference)
#include <cuda_runtime.h>
#include <math.h>
#include <stdint.h>

#define BBATCH 16
#define NPTS   4096
#define THREADS 512
#define RPT 4
#define SPLIT 2
#define HALF_PTS (NPTS / SPLIT)            // 2048 targets per block (32 KB)
#define ROWS_PER_BLOCK (THREADS * RPT)     // 2048
#define ROW_TILES (NPTS / ROWS_PER_BLOCK)  // 2
#define NPAIRS (2 * BBATCH * ROW_TILES)    // 64 merge pairs
#define GSIZE 64
#define NGROUPS (HALF_PTS / GSIZE)         // 32
#define EPSF 1e-12f

// Scratch: per (dir,b,half,row): v-domain min and absolute argmin index.
__device__ float g_vmin[2 * BBATCH * SPLIT * NPTS];
__device__ int   g_vidx[2 * BBATCH * SPLIT * NPTS];
__device__ unsigned int g_pair[NPAIRS];    // zero-init; self-resetting
__device__ float g_partials[NPAIRS];
__device__ unsigned int g_done = 0;

__device__ __forceinline__ uint64_t pack2(float lo, float hi) {
    uint64_t r;
    asm("mov.b64 %0, {%1,%2};" : "=l"(r) : "f"(lo), "f"(hi));
    return r;
}
__device__ __forceinline__ uint64_t fma2(uint64_t a, uint64_t b, uint64_t c) {
    uint64_t d;
    asm("fma.rn.f32x2 %0, %1, %2, %3;" : "=l"(d) : "l"(a), "l"(b), "l"(c));
    return d;
}
__device__ __forceinline__ void fma2_last(float& lo, float& hi,
                                          uint64_t a, uint64_t b, uint64_t c) {
    asm("{\n\t.reg .b64 t;\n\tfma.rn.f32x2 t, %2, %3, %4;\n\tmov.b64 {%0,%1}, t;\n\t}"
        : "=f"(lo), "=f"(hi) : "l"(a), "l"(b), "l"(c));
}
__device__ __forceinline__ float ldcg_f(const float* p) {
    float v; asm volatile("ld.global.cg.f32 %0, [%1];" : "=f"(v) : "l"(p)); return v;
}
__device__ __forceinline__ int ldcg_i(const int* p) {
    int v; asm volatile("ld.global.cg.s32 %0, [%1];" : "=r"(v) : "l"(p)); return v;
}

// blockIdx.x = tile*SPLIT + half  (0..3), y = batch, z = dir.
__global__ __launch_bounds__(THREADS, 1)
void chamfer_fused_kernel(const float* __restrict__ kp1,
                          const float* __restrict__ kp2,
                          const float* __restrict__ sig1,
                          const float* __restrict__ sig2,
                          float* __restrict__ out)
{
    const int tile = blockIdx.x >> 1;
    const int half = blockIdx.x & 1;
    const int b    = blockIdx.y;
    const int dir  = blockIdx.z;
    const float* qk = dir ? kp2 : kp1;
    const float* tk = dir ? kp1 : kp2;

    __shared__ __align__(16) float sx[HALF_PTS];
    __shared__ __align__(16) float sy[HALF_PTS];
    __shared__ __align__(16) float sz[HALF_PTS];
    __shared__ __align__(16) float sw[HALF_PTS];

    {   // load this half of the target set (coalesced per plane)
        const float* tp = tk + (size_t)b * 3 * NPTS + half * HALF_PTS;
        for (int i = threadIdx.x; i < HALF_PTS; i += THREADS) {
            float x = tp[i];
            float y = tp[NPTS + i];
            float z = tp[2 * NPTS + i];
            sx[i] = x; sy[i] = y; sz[i] = z;
            sw[i] = fmaf(x, x, fmaf(y, y, z * z));
        }
    }
    __syncthreads();

    const float* qp = qk + (size_t)b * 3 * NPTS;
    const int row0 = tile * ROWS_PER_BLOCK + threadIdx.x;
    uint64_t ax2[RPT], ay2[RPT], az2[RPT];
    float    best[RPT];
    int      bg[RPT];

    #pragma unroll
    for (int r = 0; r < RPT; r++) {
        const int m = row0 + r * THREADS;
        float x = qp[m], y = qp[NPTS + m], z = qp[2 * NPTS + m];
        ax2[r] = pack2(-2.0f * x, -2.0f * x);
        ay2[r] = pack2(-2.0f * y, -2.0f * y);
        az2[r] = pack2(-2.0f * z, -2.0f * z);
        best[r] = __int_as_float(0x7f800000);   // +inf
        bg[r] = 0;
    }
    const float INF = __int_as_float(0x7f800000);

    // v = ||p||^2 - 2 a.p (same argmin as d^2). Packed FMA chain; two scalar
    // FMNMX chains per row; winning 64-group replayed for the exact index.
    for (int g = 0; g < NGROUPS; g++) {
        float c1[RPT], c2[RPT];
        #pragma unroll
        for (int r = 0; r < RPT; r++) { c1[r] = INF; c2[r] = INF; }

        const int base = g * GSIZE;
        #pragma unroll 4
        for (int k = 0; k < GSIZE; k += 4) {
            const int n = base + k;
            ulonglong2 X = *(const ulonglong2*)(sx + n);
            ulonglong2 Y = *(const ulonglong2*)(sy + n);
            ulonglong2 Z = *(const ulonglong2*)(sz + n);
            ulonglong2 W = *(const ulonglong2*)(sw + n);
            #pragma unroll
            for (int r = 0; r < RPT; r++) {
                float l0, h0, l1, h1;
                fma2_last(l0, h0, ax2[r], X.x,
                          fma2(ay2[r], Y.x, fma2(az2[r], Z.x, W.x)));
                fma2_last(l1, h1, ax2[r], X.y,
                          fma2(ay2[r], Y.y, fma2(az2[r], Z.y, W.y)));
                c1[r] = fminf(c1[r], fminf(l0, h0));
                c2[r] = fminf(c2[r], fminf(l1, h1));
            }
        }
        #pragma unroll
        for (int r = 0; r < RPT; r++) {
            float gm = fminf(c1[r], c2[r]);
            bg[r]   = (gm < best[r]) ? g : bg[r];   // strict < -> earliest group
            best[r] = fminf(best[r], gm);
        }
    }

    // Replay winning group (identical scalar FMA chain -> exact first index).
    // Query coords reloaded from global (register diet through the main loop).
    int bidx[RPT];
    #pragma unroll
    for (int r = 0; r < RPT; r++) {
        const int m = row0 + r * THREADS;
        float nx = -2.0f * qp[m];
        float ny = -2.0f * qp[NPTS + m];
        float nz = -2.0f * qp[2 * NPTS + m];
        const int base = bg[r] * GSIZE;
        float lb = INF;
        int   bi = base;
        #pragma unroll 4
        for (int k = 0; k < GSIZE; k++) {
            const int n = base + k;
            float v = fmaf(nx, sx[n], fmaf(ny, sy[n], fmaf(nz, sz[n], sw[n])));
            bi = (v < lb) ? n : bi;                 // strict < keeps first index
            lb = fminf(lb, v);
        }
        bidx[r] = bi + half * HALF_PTS;             // absolute target index
    }

    // Publish this half's results.
    const size_t sb = (((size_t)(dir * BBATCH + b)) * SPLIT + half) * NPTS;
    #pragma unroll
    for (int r = 0; r < RPT; r++) {
        const int m = row0 + r * THREADS;
        g_vmin[sb + m] = best[r];
        g_vidx[sb + m] = bidx[r];
    }

    // Pair rendezvous: second finisher merges halves and computes the loss.
    const int pair_id = (dir * BBATCH + b) * ROW_TILES + tile;
    __shared__ int s_second;
    __threadfence();
    __syncthreads();
    if (threadIdx.x == 0)
        s_second = (atomicAdd(&g_pair[pair_id], 1u) == 1);
    __syncthreads();
    if (!s_second) return;
    __threadfence();

    // Read peer half's results (L2, bypass non-coherent L1).
    const size_t po = (((size_t)(dir * BBATCH + b)) * SPLIT + (half ^ 1)) * NPTS;
    float acc = 0.0f;
    const float* qs = (dir ? sig2 : sig1) + (size_t)b * NPTS;
    const float* ts = (dir ? sig1 : sig2) + (size_t)b * NPTS;
    #pragma unroll
    for (int r = 0; r < RPT; r++) {
        const int m = row0 + r * THREADS;
        float vo = ldcg_f(g_vmin + po + m);
        int   io = ldcg_i(g_vidx + po + m);
        // half0 wins ties (lower absolute index = first occurrence)
        float v0 = half ? vo : best[r];
        int   i0 = half ? io : bidx[r];
        float v1 = half ? best[r] : vo;
        int   i1 = half ? bidx[r] : io;
        bool use0 = (v0 <= v1);
        float vmin = use0 ? v0 : v1;
        int   bi   = use0 ? i0 : i1;

        // recompute ||a||^2 here (kept out of main-loop registers)
        float x = qp[m], y = qp[NPTS + m], z = qp[2 * NPTS + m];
        float sqa = fmaf(x, x, fmaf(y, y, z * z));
        float d2   = vmin + sqa;
        float mind = sqrtf(fmaxf(d2, EPSF));
        float sg   = 0.5f * (qs[m] + ts[bi]);
        acc += logf(sg) + mind / sg;
    }

    // Block reduction -> per-pair partial (fixed order -> deterministic,
    // identical whichever block of the pair runs it).
    __shared__ float red[THREADS];
    __shared__ int   s_last;
    red[threadIdx.x] = acc;
    __syncthreads();
    #pragma unroll
    for (int s = THREADS / 2; s > 32; s >>= 1) {
        if (threadIdx.x < s) red[threadIdx.x] += red[threadIdx.x + s];
        __syncthreads();
    }
    if (threadIdx.x < 32) {
        float v = red[threadIdx.x] + red[threadIdx.x + 32];
        #pragma unroll
        for (int o = 16; o > 0; o >>= 1)
            v += __shfl_down_sync(0xffffffffu, v, o);
        if (threadIdx.x == 0) {
            g_partials[pair_id] = v;
            g_pair[pair_id] = 0;            // reset for next graph replay
            __threadfence();
            unsigned int old = atomicAdd(&g_done, 1u);
            s_last = (old == NPAIRS - 1);
        }
    }
    __syncthreads();

    // Last pair-merger folds the 64 partials (fixed-order tree).
    if (s_last) {
        __threadfence();
        __shared__ double dred[NPAIRS];
        if (threadIdx.x < NPAIRS)
            dred[threadIdx.x] = (double)ldcg_f(g_partials + threadIdx.x);
        __syncthreads();
        for (int s = NPAIRS / 2; s > 0; s >>= 1) {
            if (threadIdx.x < s) dred[threadIdx.x] += dred[threadIdx.x + s];
            __syncthreads();
        }
        if (threadIdx.x == 0) {
            out[0] = (float)(dred[0] * (1.0 / ((double)BBATCH * (double)NPTS)));
            g_done = 0;                     // reset for next graph replay
        }
    }
}

extern "C" void kernel_launch(void* const* d_in, const int* in_sizes, int n_in,
                              void* d_out, int out_size)
{
    (void)in_sizes; (void)n_in; (void)out_size;
    const float* kp1  = (const float*)d_in[0];  // [B, 3, M]
    const float* kp2  = (const float*)d_in[1];  // [B, 3, N]
    const float* sig1 = (const float*)d_in[2];  // [B, M]
    const float* sig2 = (const float*)d_in[3];  // [B, N]
    float* out = (float*)d_out;

    dim3 grid(ROW_TILES * SPLIT, BBATCH, 2);    // 4 x 16 x 2 = 128 blocks
    chamfer_fused_kernel<<<grid, THREADS>>>(kp1, kp2, sig1, sig2, out);
}

// round 12
// speedup vs baseline: 1.0272x; 1.0272x over previous
#include <cuda_runtime.h>
#include <math.h>
#include <stdint.h>

#define BBATCH 16
#define NPTS   4096
#define THREADS 256
#define RPT 4
#define SPLIT 4
#define PIECE_PTS (NPTS / SPLIT)           // 1024 targets per block (16 KB)
#define ROWS_PER_BLOCK (THREADS * RPT)     // 1024
#define ROW_TILES (NPTS / ROWS_PER_BLOCK)  // 4
#define NGRP (2 * BBATCH * ROW_TILES)      // 128 rendezvous groups (dir,b,tile)
#define GSIZE 32
#define NGROUPS (PIECE_PTS / GSIZE)        // 32
#define EPSF 1e-12f

// Scratch: per (dir,b,piece,row): v-domain min and absolute argmin index.
__device__ float g_vmin[2 * BBATCH * SPLIT * NPTS];
__device__ int   g_vidx[2 * BBATCH * SPLIT * NPTS];
__device__ unsigned int g_grp[NGRP];       // zero-init; self-resetting
__device__ float g_partials[NGRP];
__device__ unsigned int g_done = 0;

__device__ __forceinline__ uint64_t pack2(float lo, float hi) {
    uint64_t r;
    asm("mov.b64 %0, {%1,%2};" : "=l"(r) : "f"(lo), "f"(hi));
    return r;
}
__device__ __forceinline__ uint64_t fma2(uint64_t a, uint64_t b, uint64_t c) {
    uint64_t d;
    asm("fma.rn.f32x2 %0, %1, %2, %3;" : "=l"(d) : "l"(a), "l"(b), "l"(c));
    return d;
}
__device__ __forceinline__ void fma2_last(float& lo, float& hi,
                                          uint64_t a, uint64_t b, uint64_t c) {
    asm("{\n\t.reg .b64 t;\n\tfma.rn.f32x2 t, %2, %3, %4;\n\tmov.b64 {%0,%1}, t;\n\t}"
        : "=f"(lo), "=f"(hi) : "l"(a), "l"(b), "l"(c));
}
__device__ __forceinline__ float ldcg_f(const float* p) {
    float v; asm volatile("ld.global.cg.f32 %0, [%1];" : "=f"(v) : "l"(p)); return v;
}
__device__ __forceinline__ int ldcg_i(const int* p) {
    int v; asm volatile("ld.global.cg.s32 %0, [%1];" : "=r"(v) : "l"(p)); return v;
}

// blockIdx.x = tile*SPLIT + piece (0..15), y = batch, z = dir.
__global__ __launch_bounds__(THREADS, 3)
void chamfer_fused_kernel(const float* __restrict__ kp1,
                          const float* __restrict__ kp2,
                          const float* __restrict__ sig1,
                          const float* __restrict__ sig2,
                          float* __restrict__ out)
{
    const int tile  = blockIdx.x >> 2;
    const int piece = blockIdx.x & 3;
    const int b     = blockIdx.y;
    const int dir   = blockIdx.z;
    const float* qk = dir ? kp2 : kp1;
    const float* tk = dir ? kp1 : kp2;

    __shared__ __align__(16) float sx[PIECE_PTS];
    __shared__ __align__(16) float sy[PIECE_PTS];
    __shared__ __align__(16) float sz[PIECE_PTS];
    __shared__ __align__(16) float sw[PIECE_PTS];

    {   // load this piece of the target set (coalesced per plane)
        const float* tp = tk + (size_t)b * 3 * NPTS + piece * PIECE_PTS;
        for (int i = threadIdx.x; i < PIECE_PTS; i += THREADS) {
            float x = tp[i];
            float y = tp[NPTS + i];
            float z = tp[2 * NPTS + i];
            sx[i] = x; sy[i] = y; sz[i] = z;
            sw[i] = fmaf(x, x, fmaf(y, y, z * z));
        }
    }
    __syncthreads();

    const float* qp = qk + (size_t)b * 3 * NPTS;
    const int row0 = tile * ROWS_PER_BLOCK + threadIdx.x;
    uint64_t ax2[RPT], ay2[RPT], az2[RPT];
    float    best[RPT];
    int      bg[RPT];

    #pragma unroll
    for (int r = 0; r < RPT; r++) {
        const int m = row0 + r * THREADS;
        float x = qp[m], y = qp[NPTS + m], z = qp[2 * NPTS + m];
        ax2[r] = pack2(-2.0f * x, -2.0f * x);
        ay2[r] = pack2(-2.0f * y, -2.0f * y);
        az2[r] = pack2(-2.0f * z, -2.0f * z);
        best[r] = __int_as_float(0x7f800000);   // +inf
        bg[r] = 0;
    }
    const float INF = __int_as_float(0x7f800000);

    // v = ||p||^2 - 2 a.p (same argmin as d^2). Packed FMA chain; one scalar
    // FMNMX chain per row (register diet); winning 32-group replayed after.
    for (int g = 0; g < NGROUPS; g++) {
        float c[RPT];
        #pragma unroll
        for (int r = 0; r < RPT; r++) c[r] = INF;

        const int base = g * GSIZE;
        #pragma unroll 2
        for (int k = 0; k < GSIZE; k += 4) {
            const int n = base + k;
            ulonglong2 X = *(const ulonglong2*)(sx + n);
            ulonglong2 Y = *(const ulonglong2*)(sy + n);
            ulonglong2 Z = *(const ulonglong2*)(sz + n);
            ulonglong2 W = *(const ulonglong2*)(sw + n);
            #pragma unroll
            for (int r = 0; r < RPT; r++) {
                float l0, h0, l1, h1;
                fma2_last(l0, h0, ax2[r], X.x,
                          fma2(ay2[r], Y.x, fma2(az2[r], Z.x, W.x)));
                fma2_last(l1, h1, ax2[r], X.y,
                          fma2(ay2[r], Y.y, fma2(az2[r], Z.y, W.y)));
                c[r] = fminf(c[r], fminf(l0, h0));
                c[r] = fminf(c[r], fminf(l1, h1));
            }
        }
        #pragma unroll
        for (int r = 0; r < RPT; r++) {
            bg[r]   = (c[r] < best[r]) ? g : bg[r];   // strict < -> earliest group
            best[r] = fminf(best[r], c[r]);
        }
    }

    // Replay winning group (identical scalar FMA chain -> exact first index).
    // Query coords reloaded from global (register diet through the main loop).
    const size_t sb = (((size_t)(dir * BBATCH + b)) * SPLIT + piece) * NPTS;
    #pragma unroll
    for (int r = 0; r < RPT; r++) {
        const int m = row0 + r * THREADS;
        float nx = -2.0f * qp[m];
        float ny = -2.0f * qp[NPTS + m];
        float nz = -2.0f * qp[2 * NPTS + m];
        const int base = bg[r] * GSIZE;
        float lb = INF;
        int   bi = base;
        #pragma unroll 4
        for (int k = 0; k < GSIZE; k++) {
            const int n = base + k;
            float v = fmaf(nx, sx[n], fmaf(ny, sy[n], fmaf(nz, sz[n], sw[n])));
            bi = (v < lb) ? n : bi;                 // strict < keeps first index
            lb = fminf(lb, v);
        }
        g_vmin[sb + m] = best[r];
        g_vidx[sb + m] = bi + piece * PIECE_PTS;    // absolute target index
    }

    // Rendezvous: the 4th finisher of (dir,b,tile) merges all pieces.
    const int grp = (dir * BBATCH + b) * ROW_TILES + tile;
    __shared__ int s_doit;
    __threadfence();
    __syncthreads();
    if (threadIdx.x == 0)
        s_doit = (atomicAdd(&g_grp[grp], 1u) == SPLIT - 1);
    __syncthreads();
    if (!s_doit) return;
    __threadfence();

    const size_t gb = (((size_t)(dir * BBATCH + b)) * SPLIT) * NPTS;
    float acc = 0.0f;
    const float* qs = (dir ? sig2 : sig1) + (size_t)b * NPTS;
    const float* ts = (dir ? sig1 : sig2) + (size_t)b * NPTS;
    #pragma unroll
    for (int r = 0; r < RPT; r++) {
        const int m = row0 + r * THREADS;
        float vmin = ldcg_f(g_vmin + gb + m);
        int   bi   = ldcg_i(g_vidx + gb + m);
        #pragma unroll
        for (int p = 1; p < SPLIT; p++) {
            float vp = ldcg_f(g_vmin + gb + (size_t)p * NPTS + m);
            int   ip = ldcg_i(g_vidx + gb + (size_t)p * NPTS + m);
            bi   = (vp < vmin) ? ip : bi;   // strict < -> earliest piece on ties
            vmin = fminf(vmin, vp);
        }
        float x = qp[m], y = qp[NPTS + m], z = qp[2 * NPTS + m];
        float sqa = fmaf(x, x, fmaf(y, y, z * z));
        float d2  = vmin + sqa;
        float mind = sqrtf(fmaxf(d2, EPSF));
        float sg = 0.5f * (qs[m] + ts[bi]);
        acc += logf(sg) + mind / sg;
    }

    // Block reduction -> per-group partial (fixed order -> deterministic,
    // identical whichever block of the group runs it).
    __shared__ float red[THREADS];
    __shared__ int   s_last;
    red[threadIdx.x] = acc;
    __syncthreads();
    #pragma unroll
    for (int s = THREADS / 2; s > 32; s >>= 1) {
        if (threadIdx.x < s) red[threadIdx.x] += red[threadIdx.x + s];
        __syncthreads();
    }
    if (threadIdx.x < 32) {
        float v = red[threadIdx.x] + red[threadIdx.x + 32];
        #pragma unroll
        for (int o = 16; o > 0; o >>= 1)
            v += __shfl_down_sync(0xffffffffu, v, o);
        if (threadIdx.x == 0) {
            g_partials[grp] = v;
            g_grp[grp] = 0;                 // reset for next graph replay
            __threadfence();
            unsigned int old = atomicAdd(&g_done, 1u);
            s_last = (old == NGRP - 1);
        }
    }
    __syncthreads();

    // Last group-merger folds the 128 partials (fixed-order tree).
    if (s_last) {
        __threadfence();
        __shared__ double dred[NGRP];
        if (threadIdx.x < NGRP)
            dred[threadIdx.x] = (double)ldcg_f(g_partials + threadIdx.x);
        __syncthreads();
        for (int s = NGRP / 2; s > 0; s >>= 1) {
            if (threadIdx.x < s) dred[threadIdx.x] += dred[threadIdx.x + s];
            __syncthreads();
        }
        if (threadIdx.x == 0) {
            out[0] = (float)(dred[0] * (1.0 / ((double)BBATCH * (double)NPTS)));
            g_done = 0;                     // reset for next graph replay
        }
    }
}

extern "C" void kernel_launch(void* const* d_in, const int* in_sizes, int n_in,
                              void* d_out, int out_size)
{
    (void)in_sizes; (void)n_in; (void)out_size;
    const float* kp1  = (const float*)d_in[0];  // [B, 3, M]
    const float* kp2  = (const float*)d_in[1];  // [B, 3, N]
    const float* sig1 = (const float*)d_in[2];  // [B, M]
    const float* sig2 = (const float*)d_in[3];  // [B, N]
    float* out = (float*)d_out;

    dim3 grid(ROW_TILES * SPLIT, BBATCH, 2);    // 16 x 16 x 2 = 512 blocks
    chamfer_fused_kernel<<<grid, THREADS>>>(kp1, kp2, sig1, sig2, out);
}

// round 13
// speedup vs baseline: 1.2582x; 1.2248x over previous
#include <cuda_runtime.h>
#include <math.h>
#include <stdint.h>

#define BBATCH 16
#define NPTS   4096
#define THREADS 512
#define RPT 4
#define SPLIT 2
#define HALF_PTS (NPTS / SPLIT)            // 2048 targets per block (32 KB)
#define ROWS_PER_BLOCK (THREADS * RPT)     // 2048
#define ROW_TILES (NPTS / ROWS_PER_BLOCK)  // 2
#define NPAIRS (2 * BBATCH * ROW_TILES)    // 64 merge pairs
#define GSIZE 32
#define NGROUPS (HALF_PTS / GSIZE)         // 64
#define EPSF 1e-12f

// Scratch: per (dir,b,half,row): v-domain min and absolute argmin index.
__device__ float g_vmin[2 * BBATCH * SPLIT * NPTS];
__device__ int   g_vidx[2 * BBATCH * SPLIT * NPTS];
__device__ unsigned int g_pair[NPAIRS];    // zero-init; self-resetting
__device__ float g_partials[NPAIRS];
__device__ unsigned int g_done = 0;

__device__ __forceinline__ uint64_t pack2(float lo, float hi) {
    uint64_t r;
    asm("mov.b64 %0, {%1,%2};" : "=l"(r) : "f"(lo), "f"(hi));
    return r;
}
__device__ __forceinline__ uint64_t fma2(uint64_t a, uint64_t b, uint64_t c) {
    uint64_t d;
    asm("fma.rn.f32x2 %0, %1, %2, %3;" : "=l"(d) : "l"(a), "l"(b), "l"(c));
    return d;
}
__device__ __forceinline__ void fma2_last(float& lo, float& hi,
                                          uint64_t a, uint64_t b, uint64_t c) {
    asm("{\n\t.reg .b64 t;\n\tfma.rn.f32x2 t, %2, %3, %4;\n\tmov.b64 {%0,%1}, t;\n\t}"
        : "=f"(lo), "=f"(hi) : "l"(a), "l"(b), "l"(c));
}
__device__ __forceinline__ float ldcg_f(const float* p) {
    float v; asm volatile("ld.global.cg.f32 %0, [%1];" : "=f"(v) : "l"(p)); return v;
}
__device__ __forceinline__ int ldcg_i(const int* p) {
    int v; asm volatile("ld.global.cg.s32 %0, [%1];" : "=r"(v) : "l"(p)); return v;
}

// blockIdx.x = tile*SPLIT + half  (0..3), y = batch, z = dir.
__global__ __launch_bounds__(THREADS, 1)
void chamfer_fused_kernel(const float* __restrict__ kp1,
                          const float* __restrict__ kp2,
                          const float* __restrict__ sig1,
                          const float* __restrict__ sig2,
                          float* __restrict__ out)
{
    const int tile = blockIdx.x >> 1;
    const int half = blockIdx.x & 1;
    const int b    = blockIdx.y;
    const int dir  = blockIdx.z;
    const float* qk = dir ? kp2 : kp1;
    const float* tk = dir ? kp1 : kp2;

    // +4 floats padding so the final (dead) prefetch stays in-bounds.
    __shared__ __align__(16) float sx[HALF_PTS + 4];
    __shared__ __align__(16) float sy[HALF_PTS + 4];
    __shared__ __align__(16) float sz[HALF_PTS + 4];
    __shared__ __align__(16) float sw[HALF_PTS + 4];

    {   // load this half of the target set (coalesced per plane)
        const float* tp = tk + (size_t)b * 3 * NPTS + half * HALF_PTS;
        for (int i = threadIdx.x; i < HALF_PTS; i += THREADS) {
            float x = tp[i];
            float y = tp[NPTS + i];
            float z = tp[2 * NPTS + i];
            sx[i] = x; sy[i] = y; sz[i] = z;
            sw[i] = fmaf(x, x, fmaf(y, y, z * z));
        }
        if (threadIdx.x < 4) {  // init padding (never used in results)
            sx[HALF_PTS + threadIdx.x] = 0.0f;
            sy[HALF_PTS + threadIdx.x] = 0.0f;
            sz[HALF_PTS + threadIdx.x] = 0.0f;
            sw[HALF_PTS + threadIdx.x] = 0.0f;
        }
    }
    __syncthreads();

    const float* qp = qk + (size_t)b * 3 * NPTS;
    const int row0 = tile * ROWS_PER_BLOCK + threadIdx.x;
    uint64_t ax2[RPT], ay2[RPT], az2[RPT];
    float    best[RPT];
    int      bg[RPT];

    #pragma unroll
    for (int r = 0; r < RPT; r++) {
        const int m = row0 + r * THREADS;
        float x = qp[m], y = qp[NPTS + m], z = qp[2 * NPTS + m];
        ax2[r] = pack2(-2.0f * x, -2.0f * x);
        ay2[r] = pack2(-2.0f * y, -2.0f * y);
        az2[r] = pack2(-2.0f * z, -2.0f * z);
        best[r] = __int_as_float(0x7f800000);   // +inf
        bg[r] = 0;
    }
    const float INF = __int_as_float(0x7f800000);

    // v = ||p||^2 - 2 a.p (same argmin as d^2). Software-pipelined: double-
    // buffered A/B register tiles keep consumers one load-batch behind
    // producers, hiding the ~29-cyc LDS latency. Winning 32-group replayed
    // afterwards for the exact first-argmin index.
    ulonglong2 XA = *(const ulonglong2*)(sx);
    ulonglong2 YA = *(const ulonglong2*)(sy);
    ulonglong2 ZA = *(const ulonglong2*)(sz);
    ulonglong2 WA = *(const ulonglong2*)(sw);

    for (int g = 0; g < NGROUPS; g++) {
        float c1[RPT], c2[RPT];
        #pragma unroll
        for (int r = 0; r < RPT; r++) { c1[r] = INF; c2[r] = INF; }

        const int base = g * GSIZE;
        #pragma unroll
        for (int kk = 0; kk < GSIZE; kk += 8) {
            const int nB = base + kk + 4;
            ulonglong2 XB = *(const ulonglong2*)(sx + nB);
            ulonglong2 YB = *(const ulonglong2*)(sy + nB);
            ulonglong2 ZB = *(const ulonglong2*)(sz + nB);
            ulonglong2 WB = *(const ulonglong2*)(sw + nB);
            #pragma unroll
            for (int r = 0; r < RPT; r++) {
                float l0, h0, l1, h1;
                fma2_last(l0, h0, ax2[r], XA.x,
                          fma2(ay2[r], YA.x, fma2(az2[r], ZA.x, WA.x)));
                fma2_last(l1, h1, ax2[r], XA.y,
                          fma2(ay2[r], YA.y, fma2(az2[r], ZA.y, WA.y)));
                c1[r] = fminf(c1[r], fminf(l0, h0));
                c2[r] = fminf(c2[r], fminf(l1, h1));
            }
            const int nA = base + kk + 8;   // crosses group boundary / padding
            XA = *(const ulonglong2*)(sx + nA);
            YA = *(const ulonglong2*)(sy + nA);
            ZA = *(const ulonglong2*)(sz + nA);
            WA = *(const ulonglong2*)(sw + nA);
            #pragma unroll
            for (int r = 0; r < RPT; r++) {
                float l0, h0, l1, h1;
                fma2_last(l0, h0, ax2[r], XB.x,
                          fma2(ay2[r], YB.x, fma2(az2[r], ZB.x, WB.x)));
                fma2_last(l1, h1, ax2[r], XB.y,
                          fma2(ay2[r], YB.y, fma2(az2[r], ZB.y, WB.y)));
                c1[r] = fminf(c1[r], fminf(l0, h0));
                c2[r] = fminf(c2[r], fminf(l1, h1));
            }
        }
        #pragma unroll
        for (int r = 0; r < RPT; r++) {
            float gm = fminf(c1[r], c2[r]);
            bg[r]   = (gm < best[r]) ? g : bg[r];   // strict < -> earliest group
            best[r] = fminf(best[r], gm);
        }
    }

    // Replay winning group (identical scalar FMA chain -> exact first index).
    // Query coords reloaded from global (register diet through the main loop).
    int bidx[RPT];
    #pragma unroll
    for (int r = 0; r < RPT; r++) {
        const int m = row0 + r * THREADS;
        float nx = -2.0f * qp[m];
        float ny = -2.0f * qp[NPTS + m];
        float nz = -2.0f * qp[2 * NPTS + m];
        const int base = bg[r] * GSIZE;
        float lb = INF;
        int   bi = base;
        #pragma unroll 4
        for (int k = 0; k < GSIZE; k++) {
            const int n = base + k;
            float v = fmaf(nx, sx[n], fmaf(ny, sy[n], fmaf(nz, sz[n], sw[n])));
            bi = (v < lb) ? n : bi;                 // strict < keeps first index
            lb = fminf(lb, v);
        }
        bidx[r] = bi + half * HALF_PTS;             // absolute target index
    }

    // Publish this half's results.
    const size_t sb = (((size_t)(dir * BBATCH + b)) * SPLIT + half) * NPTS;
    #pragma unroll
    for (int r = 0; r < RPT; r++) {
        const int m = row0 + r * THREADS;
        g_vmin[sb + m] = best[r];
        g_vidx[sb + m] = bidx[r];
    }

    // Pair rendezvous: second finisher merges halves and computes the loss.
    const int pair_id = (dir * BBATCH + b) * ROW_TILES + tile;
    __shared__ int s_second;
    __threadfence();
    __syncthreads();
    if (threadIdx.x == 0)
        s_second = (atomicAdd(&g_pair[pair_id], 1u) == 1);
    __syncthreads();
    if (!s_second) return;
    __threadfence();

    // Read peer half's results (L2, bypass non-coherent L1).
    const size_t po = (((size_t)(dir * BBATCH + b)) * SPLIT + (half ^ 1)) * NPTS;
    float acc = 0.0f;
    const float* qs = (dir ? sig2 : sig1) + (size_t)b * NPTS;
    const float* ts = (dir ? sig1 : sig2) + (size_t)b * NPTS;
    #pragma unroll
    for (int r = 0; r < RPT; r++) {
        const int m = row0 + r * THREADS;
        float vo = ldcg_f(g_vmin + po + m);
        int   io = ldcg_i(g_vidx + po + m);
        // half0 wins ties (lower absolute index = first occurrence)
        float v0 = half ? vo : best[r];
        int   i0 = half ? io : bidx[r];
        float v1 = half ? best[r] : vo;
        int   i1 = half ? bidx[r] : io;
        bool use0 = (v0 <= v1);
        float vmin = use0 ? v0 : v1;
        int   bi   = use0 ? i0 : i1;

        float x = qp[m], y = qp[NPTS + m], z = qp[2 * NPTS + m];
        float sqa = fmaf(x, x, fmaf(y, y, z * z));
        float d2   = vmin + sqa;
        float mind = sqrtf(fmaxf(d2, EPSF));
        float sg   = 0.5f * (qs[m] + ts[bi]);
        acc += logf(sg) + mind / sg;
    }

    // Block reduction -> per-pair partial (fixed order -> deterministic,
    // identical whichever block of the pair runs it).
    __shared__ float red[THREADS];
    __shared__ int   s_last;
    red[threadIdx.x] = acc;
    __syncthreads();
    #pragma unroll
    for (int s = THREADS / 2; s > 32; s >>= 1) {
        if (threadIdx.x < s) red[threadIdx.x] += red[threadIdx.x + s];
        __syncthreads();
    }
    if (threadIdx.x < 32) {
        float v = red[threadIdx.x] + red[threadIdx.x + 32];
        #pragma unroll
        for (int o = 16; o > 0; o >>= 1)
            v += __shfl_down_sync(0xffffffffu, v, o);
        if (threadIdx.x == 0) {
            g_partials[pair_id] = v;
            g_pair[pair_id] = 0;            // reset for next graph replay
            __threadfence();
            unsigned int old = atomicAdd(&g_done, 1u);
            s_last = (old == NPAIRS - 1);
        }
    }
    __syncthreads();

    // Last pair-merger folds the 64 partials (fixed-order tree).
    if (s_last) {
        __threadfence();
        __shared__ double dred[NPAIRS];
        if (threadIdx.x < NPAIRS)
            dred[threadIdx.x] = (double)ldcg_f(g_partials + threadIdx.x);
        __syncthreads();
        for (int s = NPAIRS / 2; s > 0; s >>= 1) {
            if (threadIdx.x < s) dred[threadIdx.x] += dred[threadIdx.x + s];
            __syncthreads();
        }
        if (threadIdx.x == 0) {
            out[0] = (float)(dred[0] * (1.0 / ((double)BBATCH * (double)NPTS)));
            g_done = 0;                     // reset for next graph replay
        }
    }
}

extern "C" void kernel_launch(void* const* d_in, const int* in_sizes, int n_in,
                              void* d_out, int out_size)
{
    (void)in_sizes; (void)n_in; (void)out_size;
    const float* kp1  = (const float*)d_in[0];  // [B, 3, M]
    const float* kp2  = (const float*)d_in[1];  // [B, 3, N]
    const float* sig1 = (const float*)d_in[2];  // [B, M]
    const float* sig2 = (const float*)d_in[3];  // [B, N]
    float* out = (float*)d_out;

    dim3 grid(ROW_TILES * SPLIT, BBATCH, 2);    // 4 x 16 x 2 = 128 blocks
    chamfer_fused_kernel<<<grid, THREADS>>>(kp1, kp2, sig1, sig2, out);
}